// round 12
// baseline (speedup 1.0000x reference)
#include <cuda_runtime.h>

typedef unsigned long long u64;

#define Bn 4096
#define Tn 128
#define Dn 32
#define Hn 64
#define Gn 192   // 3*H

#define NWARP 16
#define TPB (NWARP * 32)  // 512 threads
#define NPAIR 8           // warp pairs per block
#define EPW 4             // batch elements per warp PAIR
#define EPB (NPAIR * EPW) // 32 elements per block

// Weight layout: s[(k>>2)*768 + g*4 + (k&3)] = W[g][k]
#define OFF_W0X 0
#define OFF_W0H (OFF_W0X + 8  * 768)
#define OFF_W1I (OFF_W0H + 16 * 768)
#define OFF_W1H (OFF_W1I + 16 * 768)
#define OFF_H1  (OFF_W1H + 16 * 768)              // [8 pair][2 buf][4 e][64]
#define OFF_H2  (OFF_H1 + NPAIR * 2 * EPW * Hn)
#define OFF_X   (OFF_H2 + NPAIR * 2 * EPW * Hn)   // [16 warp][4 e][32]
#define SMEM_FLOATS (OFF_X + NWARP * EPW * Dn)    // 53248 floats = 212992 B

__device__ __forceinline__ void ffma2(u64& d, u64 a, u64 b) {
    asm("fma.rn.f32x2 %0, %1, %2, %0;" : "+l"(d) : "l"(a), "l"(b));
}
__device__ __forceinline__ float hsum2(u64 v) {
    float lo, hi;
    asm("mov.b64 {%0, %1}, %2;" : "=f"(lo), "=f"(hi) : "l"(v));
    return lo + hi;
}
__device__ __forceinline__ float sigmoid_f(float x) {
    return __fdividef(1.0f, 1.0f + __expf(-x));
}
__device__ __forceinline__ float tanh_f(float x) {
    float e = __expf(-2.0f * x);
    return __fdividef(1.0f - e, 1.0f + e);
}

struct u64x2 { u64 a, b; };
__device__ __forceinline__ u64x2 lds128(const float* p) {
    u64x2 r;
    ulonglong2 v = *(const ulonglong2*)p;
    r.a = v.x; r.b = v.y;
    return r;
}

__global__ void __launch_bounds__(TPB, 1)
gru_fused_kernel(const float* __restrict__ x,
                 const float* __restrict__ W_ih0, const float* __restrict__ W_hh0,
                 const float* __restrict__ b_ih0, const float* __restrict__ b_hh0,
                 const float* __restrict__ W_ih1, const float* __restrict__ W_hh1,
                 const float* __restrict__ b_ih1, const float* __restrict__ b_hh1,
                 const float* __restrict__ fc_w, const float* __restrict__ fc_b,
                 float* __restrict__ out)
{
    extern __shared__ float sm[];
    const int tid = threadIdx.x;

    // ---- stage weights ----
    for (int idx = tid; idx < Gn * Dn; idx += TPB) {
        int g = idx / Dn, k = idx - g * Dn;
        sm[OFF_W0X + (k >> 2) * 768 + g * 4 + (k & 3)] = W_ih0[idx];
    }
    for (int idx = tid; idx < Gn * Hn; idx += TPB) {
        int g = idx / Hn, k = idx - g * Hn;
        int d = (k >> 2) * 768 + g * 4 + (k & 3);
        sm[OFF_W0H + d] = W_hh0[idx];
        sm[OFF_W1I + d] = W_ih1[idx];
        sm[OFF_W1H + d] = W_hh1[idx];
    }
    __syncthreads();

    const int warp = tid >> 5;
    const int lane = tid & 31;
    const int wg = warp >> 1;   // pair id 0..7: warps {2wg,2wg+1} — each SMSP hosts
    const int hw = warp & 1;    //   4 warps from 4 INDEPENDENT pairs
    const int barid = 1 + wg;   // named barriers 1..8
    const int eb = blockIdx.x * EPB + wg * EPW;

    const int row = lane + 32 * hw;

    float* h1b = sm + OFF_H1 + wg * (2 * EPW * Hn);
    float* h2b = sm + OFF_H2 + wg * (2 * EPW * Hn);
    float* s_x = sm + OFF_X  + warp * (EPW * Dn);

#pragma unroll
    for (int e = 0; e < EPW; ++e) {
        h1b[e * Hn + row] = 0.0f;
        h2b[e * Hn + row] = 0.0f;
    }
    __syncthreads();

    const float Br0  = b_ih0[row]       + b_hh0[row];
    const float Bz0  = b_ih0[row + 64]  + b_hh0[row + 64];
    const float Bxn0 = b_ih0[row + 128];
    const float Bhn0 = b_hh0[row + 128];
    const float Br1  = b_ih1[row]       + b_hh1[row];
    const float Bz1  = b_ih1[row + 64]  + b_hh1[row + 64];
    const float Bxn1 = b_ih1[row + 128];
    const float Bhn1 = b_hh1[row + 128];

    const int oR = row * 4;
    const int oZ = (row + 64) * 4;
    const int oN = (row + 128) * 4;

    u64 ar[EPW], az[EPW], axn[EPW], ahn[EPW];

    float h1own[EPW], h2own[EPW];
#pragma unroll
    for (int e = 0; e < EPW; ++e) { h1own[e] = 0.0f; h2own[e] = 0.0f; }

    // prefetch t=0 x
    float xr[EPW];
#pragma unroll
    for (int e = 0; e < EPW; ++e)
        xr[e] = x[(eb + e) * (Tn * Dn) + lane];

    int rd = 0;

    for (int t = 0; t < Tn; ++t) {
        const float* h1r = h1b + rd * (EPW * Hn);
        float*       h1w = h1b + (1 - rd) * (EPW * Hn);
        const float* h2r = h2b + rd * (EPW * Hn);
        float*       h2w = h2b + (1 - rd) * (EPW * Hn);

        // stage x, prefetch next t
#pragma unroll
        for (int e = 0; e < EPW; ++e)
            s_x[e * Dn + lane] = xr[e];
        __syncwarp();
        if (t + 1 < Tn) {
#pragma unroll
            for (int e = 0; e < EPW; ++e)
                xr[e] = x[((eb + e) * Tn + t + 1) * Dn + lane];
        }

        // ================= layer 0 =================
#pragma unroll
        for (int e = 0; e < EPW; ++e) { ar[e] = 0; az[e] = 0; axn[e] = 0; ahn[e] = 0; }

#pragma unroll 4
        for (int q = 0; q < Dn / 4; ++q) {
            const float* wq = sm + OFF_W0X + q * 768;
            u64x2 wr = lds128(wq + oR);
            u64x2 wz = lds128(wq + oZ);
            u64x2 wn = lds128(wq + oN);
            u64x2 xv[EPW];
#pragma unroll
            for (int e = 0; e < EPW; ++e)
                xv[e] = lds128(s_x + e * Dn + q * 4);
#pragma unroll
            for (int e = 0; e < EPW; ++e) {
                ffma2(ar[e],  wr.a, xv[e].a); ffma2(ar[e],  wr.b, xv[e].b);
                ffma2(az[e],  wz.a, xv[e].a); ffma2(az[e],  wz.b, xv[e].b);
                ffma2(axn[e], wn.a, xv[e].a); ffma2(axn[e], wn.b, xv[e].b);
            }
        }
#pragma unroll 4
        for (int q = 0; q < Hn / 4; ++q) {
            const float* wq = sm + OFF_W0H + q * 768;
            u64x2 wr = lds128(wq + oR);
            u64x2 wz = lds128(wq + oZ);
            u64x2 wn = lds128(wq + oN);
            u64x2 hv[EPW];
#pragma unroll
            for (int e = 0; e < EPW; ++e)
                hv[e] = lds128(h1r + e * Hn + q * 4);
#pragma unroll
            for (int e = 0; e < EPW; ++e) {
                ffma2(ar[e],  wr.a, hv[e].a); ffma2(ar[e],  wr.b, hv[e].b);
                ffma2(az[e],  wz.a, hv[e].a); ffma2(az[e],  wz.b, hv[e].b);
                ffma2(ahn[e], wn.a, hv[e].a); ffma2(ahn[e], wn.b, hv[e].b);
            }
        }

        // epilogue -> h1_new (own row)
#pragma unroll
        for (int e = 0; e < EPW; ++e) {
            float r = sigmoid_f(hsum2(ar[e]) + Br0);
            float z = sigmoid_f(hsum2(az[e]) + Bz0);
            float n = tanh_f(fmaf(r, hsum2(ahn[e]) + Bhn0, hsum2(axn[e]) + Bxn0));
            float hn_ = fmaf(z, h1own[e] - n, n);
            h1own[e] = hn_;
            h1w[e * Hn + row] = hn_;
        }

        asm volatile("bar.sync %0, %1;" :: "r"(barid), "r"(64) : "memory");

        // ================= layer 1 =================
#pragma unroll
        for (int e = 0; e < EPW; ++e) { ar[e] = 0; az[e] = 0; axn[e] = 0; ahn[e] = 0; }

#pragma unroll 2
        for (int q = 0; q < Hn / 4; ++q) {
            const float* wqi = sm + OFF_W1I + q * 768;
            const float* wqh = sm + OFF_W1H + q * 768;
            u64x2 ir = lds128(wqi + oR);
            u64x2 iz = lds128(wqi + oZ);
            u64x2 in = lds128(wqi + oN);
            u64x2 hr = lds128(wqh + oR);
            u64x2 hz = lds128(wqh + oZ);
            u64x2 hn = lds128(wqh + oN);
            u64x2 av[EPW], bv[EPW];
#pragma unroll
            for (int e = 0; e < EPW; ++e) {
                av[e] = lds128(h1w + e * Hn + q * 4);
                bv[e] = lds128(h2r + e * Hn + q * 4);
            }
#pragma unroll
            for (int e = 0; e < EPW; ++e) {
                ffma2(ar[e],  ir.a, av[e].a); ffma2(ar[e],  ir.b, av[e].b);
                ffma2(az[e],  iz.a, av[e].a); ffma2(az[e],  iz.b, av[e].b);
                ffma2(axn[e], in.a, av[e].a); ffma2(axn[e], in.b, av[e].b);
                ffma2(ar[e],  hr.a, bv[e].a); ffma2(ar[e],  hr.b, bv[e].b);
                ffma2(az[e],  hz.a, bv[e].a); ffma2(az[e],  hz.b, bv[e].b);
                ffma2(ahn[e], hn.a, bv[e].a); ffma2(ahn[e], hn.b, bv[e].b);
            }
        }

#pragma unroll
        for (int e = 0; e < EPW; ++e) {
            float r = sigmoid_f(hsum2(ar[e]) + Br1);
            float z = sigmoid_f(hsum2(az[e]) + Bz1);
            float n = tanh_f(fmaf(r, hsum2(ahn[e]) + Bhn1, hsum2(axn[e]) + Bxn1));
            float hn_ = fmaf(z, h2own[e] - n, n);
            h2own[e] = hn_;
            h2w[e * Hn + row] = hn_;
        }

        rd ^= 1;
    }

    asm volatile("bar.sync %0, %1;" :: "r"(barid), "r"(64) : "memory");

    // ---- FC head ----
    if (hw == 0) {
        const float* h2f = h2b + rd * (EPW * Hn);
        const float fw0 = fc_w[lane];
        const float fw1 = fc_w[lane + 32];
        const float fb  = fc_b[0];
#pragma unroll
        for (int e = 0; e < EPW; ++e) {
            float v = fw0 * h2own[e] + fw1 * h2f[e * Hn + lane + 32];
#pragma unroll
            for (int off = 16; off > 0; off >>= 1)
                v += __shfl_xor_sync(0xffffffffu, v, off);
            if (lane == 0) out[eb + e] = v + fb;
        }
    }
}

extern "C" void kernel_launch(void* const* d_in, const int* in_sizes, int n_in,
                              void* d_out, int out_size)
{
    const float* x     = (const float*)d_in[0];
    const float* W_ih0 = (const float*)d_in[1];
    const float* W_hh0 = (const float*)d_in[2];
    const float* b_ih0 = (const float*)d_in[3];
    const float* b_hh0 = (const float*)d_in[4];
    const float* W_ih1 = (const float*)d_in[5];
    const float* W_hh1 = (const float*)d_in[6];
    const float* b_ih1 = (const float*)d_in[7];
    const float* b_hh1 = (const float*)d_in[8];
    const float* fc_w  = (const float*)d_in[9];
    const float* fc_b  = (const float*)d_in[10];
    float* out = (float*)d_out;

    int batch = in_sizes[0] / (Tn * Dn);   // 4096
    int grid = batch / EPB;                // 128 blocks

    size_t smem = (size_t)SMEM_FLOATS * sizeof(float);  // 212992 B
    cudaFuncSetAttribute(gru_fused_kernel,
                         cudaFuncAttributeMaxDynamicSharedMemorySize, (int)smem);

    gru_fused_kernel<<<grid, TPB, smem>>>(x, W_ih0, W_hh0, b_ih0, b_hh0,
                                          W_ih1, W_hh1, b_ih1, b_hh1,
                                          fc_w, fc_b, out);
}

// round 14
// speedup vs baseline: 1.0917x; 1.0917x over previous
#include <cuda_runtime.h>

typedef unsigned long long u64;

#define Bn 4096
#define Tn 128
#define Dn 32
#define Hn 64
#define Gn 192   // 3*H

#define NWARP 8
#define TPB (NWARP * 32)  // 256 threads
#define NPAIR 4           // warp pairs per block
#define EPW 8             // batch elements per warp PAIR
#define EPB (NPAIR * EPW) // 32 elements per block

// Weight layout: s[(k>>2)*768 + g*4 + (k&3)] = W[g][k]
#define OFF_W0X 0
#define OFF_W0H (OFF_W0X + 8  * 768)
#define OFF_W1I (OFF_W0H + 16 * 768)
#define OFF_W1H (OFF_W1I + 16 * 768)
#define OFF_H1  (OFF_W1H + 16 * 768)              // [4 pair][2 buf][8 e][64]
#define OFF_H2  (OFF_H1 + NPAIR * 2 * EPW * Hn)
#define OFF_X   (OFF_H2 + NPAIR * 2 * EPW * Hn)   // [8 warp][8 e][32]
#define SMEM_FLOATS (OFF_X + NWARP * EPW * Dn)    // 53248 floats = 212992 B

__device__ __forceinline__ void ffma2(u64& d, u64 a, u64 b) {
    asm("fma.rn.f32x2 %0, %1, %2, %0;" : "+l"(d) : "l"(a), "l"(b));
}
__device__ __forceinline__ u64 pack2(float lo, float hi) {
    u64 r; asm("mov.b64 %0, {%1, %2};" : "=l"(r) : "f"(lo), "f"(hi)); return r;
}
__device__ __forceinline__ float hsum2(u64 v) {
    float lo, hi;
    asm("mov.b64 {%0, %1}, %2;" : "=f"(lo), "=f"(hi) : "l"(v));
    return lo + hi;
}
__device__ __forceinline__ float sigmoid_f(float x) {
    return __fdividef(1.0f, 1.0f + __expf(-x));
}
__device__ __forceinline__ float tanh_f(float x) {
    float e = __expf(-2.0f * x);
    return __fdividef(1.0f - e, 1.0f + e);
}

struct u64x2 { u64 a, b; };
__device__ __forceinline__ u64x2 lds128(const float* p) {
    u64x2 r;
    ulonglong2 v = *(const ulonglong2*)p;
    r.a = v.x; r.b = v.y;
    return r;
}

__global__ void __launch_bounds__(TPB, 1)
gru_fused_kernel(const float* __restrict__ x,
                 const float* __restrict__ W_ih0, const float* __restrict__ W_hh0,
                 const float* __restrict__ b_ih0, const float* __restrict__ b_hh0,
                 const float* __restrict__ W_ih1, const float* __restrict__ W_hh1,
                 const float* __restrict__ b_ih1, const float* __restrict__ b_hh1,
                 const float* __restrict__ fc_w, const float* __restrict__ fc_b,
                 float* __restrict__ out)
{
    extern __shared__ float sm[];
    const int tid = threadIdx.x;

    // ---- stage weights ----
    for (int idx = tid; idx < Gn * Dn; idx += TPB) {
        int g = idx / Dn, k = idx - g * Dn;
        sm[OFF_W0X + (k >> 2) * 768 + g * 4 + (k & 3)] = W_ih0[idx];
    }
    for (int idx = tid; idx < Gn * Hn; idx += TPB) {
        int g = idx / Hn, k = idx - g * Hn;
        int d = (k >> 2) * 768 + g * 4 + (k & 3);
        sm[OFF_W0H + d] = W_hh0[idx];
        sm[OFF_W1I + d] = W_ih1[idx];
        sm[OFF_W1H + d] = W_hh1[idx];
    }
    __syncthreads();

    const int warp = tid >> 5;
    const int lane = tid & 31;
    const int wg = warp >> 1;         // pair id: warps {2wg,2wg+1}
    const int hw = warp & 1;          // row half
    const int barid = 1 + wg;
    const int eb = blockIdx.x * EPB + wg * EPW;

    const int row = lane + 32 * hw;

    float* h1b = sm + OFF_H1 + wg * (2 * EPW * Hn);
    float* h2b = sm + OFF_H2 + wg * (2 * EPW * Hn);
    float* s_x = sm + OFF_X  + warp * (EPW * Dn);

#pragma unroll
    for (int e = 0; e < EPW; ++e) {
        h1b[e * Hn + row] = 0.0f;
        h2b[e * Hn + row] = 0.0f;
    }
    __syncthreads();

    // ---- PHASE STAGGER: offset pair wg by ~wg * 1080 cyc so pairs stay ----
    // ---- ~90° out of phase for the whole (barrier-free across pairs) loop --
    {
        float dly = 1.0f;
        int iters = wg * 270;
        for (int i = 0; i < iters; ++i)
            asm volatile("fma.rn.f32 %0, %0, 0f3F800001, 0f33D6BF95;" : "+f"(dly));
    }

    // biases packed into accumulator-init constants (lo slot; hi = 0)
    const u64 BR0i  = pack2(b_ih0[row]       + b_hh0[row],       0.0f);
    const u64 BZ0i  = pack2(b_ih0[row + 64]  + b_hh0[row + 64],  0.0f);
    const u64 BXN0i = pack2(b_ih0[row + 128], 0.0f);
    const u64 BHN0i = pack2(b_hh0[row + 128], 0.0f);
    const u64 BR1i  = pack2(b_ih1[row]       + b_hh1[row],       0.0f);
    const u64 BZ1i  = pack2(b_ih1[row + 64]  + b_hh1[row + 64],  0.0f);
    const u64 BXN1i = pack2(b_ih1[row + 128], 0.0f);
    const u64 BHN1i = pack2(b_hh1[row + 128], 0.0f);

    const int oR = row * 4;
    const int oZ = (row + 64) * 4;
    const int oN = (row + 128) * 4;

    u64 ar[EPW], az[EPW], axn[EPW], ahn[EPW];

    float h1own[EPW], h2own[EPW];
#pragma unroll
    for (int e = 0; e < EPW; ++e) { h1own[e] = 0.0f; h2own[e] = 0.0f; }

    // prefetch t=0 x
    float xr[EPW];
#pragma unroll
    for (int e = 0; e < EPW; ++e)
        xr[e] = x[(eb + e) * (Tn * Dn) + lane];

    int rd = 0;

    for (int t = 0; t < Tn; ++t) {
        const float* h1r = h1b + rd * (EPW * Hn);
        float*       h1w = h1b + (1 - rd) * (EPW * Hn);
        const float* h2r = h2b + rd * (EPW * Hn);
        float*       h2w = h2b + (1 - rd) * (EPW * Hn);

        // stage x, prefetch next t
#pragma unroll
        for (int e = 0; e < EPW; ++e)
            s_x[e * Dn + lane] = xr[e];
        __syncwarp();
        if (t + 1 < Tn) {
#pragma unroll
            for (int e = 0; e < EPW; ++e)
                xr[e] = x[((eb + e) * Tn + t + 1) * Dn + lane];
        }

        // ================= layer 0 =================
#pragma unroll
        for (int e = 0; e < EPW; ++e) {
            ar[e] = BR0i; az[e] = BZ0i; axn[e] = BXN0i; ahn[e] = BHN0i;
        }

#pragma unroll 4
        for (int q = 0; q < Dn / 4; ++q) {
            const float* wq = sm + OFF_W0X + q * 768;
            u64x2 wr = lds128(wq + oR);
            u64x2 wz = lds128(wq + oZ);
            u64x2 wn = lds128(wq + oN);
            u64x2 xv[EPW];
#pragma unroll
            for (int e = 0; e < EPW; ++e)
                xv[e] = lds128(s_x + e * Dn + q * 4);
#pragma unroll
            for (int e = 0; e < EPW; ++e) {
                ffma2(ar[e],  wr.a, xv[e].a); ffma2(ar[e],  wr.b, xv[e].b);
                ffma2(az[e],  wz.a, xv[e].a); ffma2(az[e],  wz.b, xv[e].b);
                ffma2(axn[e], wn.a, xv[e].a); ffma2(axn[e], wn.b, xv[e].b);
            }
        }
#pragma unroll 4
        for (int q = 0; q < Hn / 4; ++q) {
            const float* wq = sm + OFF_W0H + q * 768;
            u64x2 wr = lds128(wq + oR);
            u64x2 wz = lds128(wq + oZ);
            u64x2 wn = lds128(wq + oN);
            u64x2 hv[EPW];
#pragma unroll
            for (int e = 0; e < EPW; ++e)
                hv[e] = lds128(h1r + e * Hn + q * 4);
#pragma unroll
            for (int e = 0; e < EPW; ++e) {
                ffma2(ar[e],  wr.a, hv[e].a); ffma2(ar[e],  wr.b, hv[e].b);
                ffma2(az[e],  wz.a, hv[e].a); ffma2(az[e],  wz.b, hv[e].b);
                ffma2(ahn[e], wn.a, hv[e].a); ffma2(ahn[e], wn.b, hv[e].b);
            }
        }

        // epilogue -> h1_new (own row); biases already inside accumulators
#pragma unroll
        for (int e = 0; e < EPW; ++e) {
            float r = sigmoid_f(hsum2(ar[e]));
            float z = sigmoid_f(hsum2(az[e]));
            float n = tanh_f(fmaf(r, hsum2(ahn[e]), hsum2(axn[e])));
            float hn_ = fmaf(z, h1own[e] - n, n);
            h1own[e] = hn_;
            h1w[e * Hn + row] = hn_;
        }

        // hoist layer-1 q=0 weight loads above the barrier (static data, no race)
        u64x2 p_ir, p_iz, p_in, p_hr, p_hz, p_hn;
        {
            const float* wqi = sm + OFF_W1I;
            const float* wqh = sm + OFF_W1H;
            p_ir = lds128(wqi + oR); p_iz = lds128(wqi + oZ); p_in = lds128(wqi + oN);
            p_hr = lds128(wqh + oR); p_hz = lds128(wqh + oZ); p_hn = lds128(wqh + oN);
        }

        asm volatile("bar.sync %0, %1;" :: "r"(barid), "r"(64) : "memory");

        // ================= layer 1 =================
#pragma unroll
        for (int e = 0; e < EPW; ++e) {
            ar[e] = BR1i; az[e] = BZ1i; axn[e] = BXN1i; ahn[e] = BHN1i;
        }

        // peeled q = 0 with preloaded weights
        {
            u64x2 av[EPW], bv[EPW];
#pragma unroll
            for (int e = 0; e < EPW; ++e) {
                av[e] = lds128(h1w + e * Hn);
                bv[e] = lds128(h2r + e * Hn);
            }
#pragma unroll
            for (int e = 0; e < EPW; ++e) {
                ffma2(ar[e],  p_ir.a, av[e].a); ffma2(ar[e],  p_ir.b, av[e].b);
                ffma2(az[e],  p_iz.a, av[e].a); ffma2(az[e],  p_iz.b, av[e].b);
                ffma2(axn[e], p_in.a, av[e].a); ffma2(axn[e], p_in.b, av[e].b);
                ffma2(ar[e],  p_hr.a, bv[e].a); ffma2(ar[e],  p_hr.b, bv[e].b);
                ffma2(az[e],  p_hz.a, bv[e].a); ffma2(az[e],  p_hz.b, bv[e].b);
                ffma2(ahn[e], p_hn.a, bv[e].a); ffma2(ahn[e], p_hn.b, bv[e].b);
            }
        }

#pragma unroll 3
        for (int q = 1; q < Hn / 4; ++q) {
            const float* wqi = sm + OFF_W1I + q * 768;
            const float* wqh = sm + OFF_W1H + q * 768;
            u64x2 ir = lds128(wqi + oR);
            u64x2 iz = lds128(wqi + oZ);
            u64x2 in = lds128(wqi + oN);
            u64x2 hr = lds128(wqh + oR);
            u64x2 hz = lds128(wqh + oZ);
            u64x2 hn = lds128(wqh + oN);
            u64x2 av[EPW], bv[EPW];
#pragma unroll
            for (int e = 0; e < EPW; ++e) {
                av[e] = lds128(h1w + e * Hn + q * 4);
                bv[e] = lds128(h2r + e * Hn + q * 4);
            }
#pragma unroll
            for (int e = 0; e < EPW; ++e) {
                ffma2(ar[e],  ir.a, av[e].a); ffma2(ar[e],  ir.b, av[e].b);
                ffma2(az[e],  iz.a, av[e].a); ffma2(az[e],  iz.b, av[e].b);
                ffma2(axn[e], in.a, av[e].a); ffma2(axn[e], in.b, av[e].b);
                ffma2(ar[e],  hr.a, bv[e].a); ffma2(ar[e],  hr.b, bv[e].b);
                ffma2(az[e],  hz.a, bv[e].a); ffma2(az[e],  hz.b, bv[e].b);
                ffma2(ahn[e], hn.a, bv[e].a); ffma2(ahn[e], hn.b, bv[e].b);
            }
        }

#pragma unroll
        for (int e = 0; e < EPW; ++e) {
            float r = sigmoid_f(hsum2(ar[e]));
            float z = sigmoid_f(hsum2(az[e]));
            float n = tanh_f(fmaf(r, hsum2(ahn[e]), hsum2(axn[e])));
            float hn_ = fmaf(z, h2own[e] - n, n);
            h2own[e] = hn_;
            h2w[e * Hn + row] = hn_;
        }

        rd ^= 1;
    }

    asm volatile("bar.sync %0, %1;" :: "r"(barid), "r"(64) : "memory");

    // ---- FC head ----
    if (hw == 0) {
        const float* h2f = h2b + rd * (EPW * Hn);
        const float fw0 = fc_w[lane];
        const float fw1 = fc_w[lane + 32];
        const float fb  = fc_b[0];
#pragma unroll
        for (int e = 0; e < EPW; ++e) {
            float v = fw0 * h2own[e] + fw1 * h2f[e * Hn + lane + 32];
#pragma unroll
            for (int off = 16; off > 0; off >>= 1)
                v += __shfl_xor_sync(0xffffffffu, v, off);
            if (lane == 0) out[eb + e] = v + fb;
        }
    }
}

extern "C" void kernel_launch(void* const* d_in, const int* in_sizes, int n_in,
                              void* d_out, int out_size)
{
    const float* x     = (const float*)d_in[0];
    const float* W_ih0 = (const float*)d_in[1];
    const float* W_hh0 = (const float*)d_in[2];
    const float* b_ih0 = (const float*)d_in[3];
    const float* b_hh0 = (const float*)d_in[4];
    const float* W_ih1 = (const float*)d_in[5];
    const float* W_hh1 = (const float*)d_in[6];
    const float* b_ih1 = (const float*)d_in[7];
    const float* b_hh1 = (const float*)d_in[8];
    const float* fc_w  = (const float*)d_in[9];
    const float* fc_b  = (const float*)d_in[10];
    float* out = (float*)d_out;

    int batch = in_sizes[0] / (Tn * Dn);   // 4096
    int grid = batch / EPB;                // 128 blocks

    size_t smem = (size_t)SMEM_FLOATS * sizeof(float);  // 212992 B
    cudaFuncSetAttribute(gru_fused_kernel,
                         cudaFuncAttributeMaxDynamicSharedMemorySize, (int)smem);

    gru_fused_kernel<<<grid, TPB, smem>>>(x, W_ih0, W_hh0, b_ih0, b_hh0,
                                          W_ih1, W_hh1, b_ih1, b_hh1,
                                          fc_w, fc_b, out);
}

// round 15
// speedup vs baseline: 1.1936x; 1.0933x over previous
#include <cuda_runtime.h>

typedef unsigned long long u64;

#define Bn 4096
#define Tn 128
#define Dn 32
#define Hn 64
#define Gn 192   // 3*H

#define NWARP 8
#define TPB (NWARP * 32)  // 256 threads
#define NPAIR 4           // warp pairs per block
#define EPW 7             // batch elements per warp PAIR (was 8)
#define EPB (NPAIR * EPW) // 28 elements per block -> grid 147 (~full 148-SM wave)

// Weight layout: s[(k>>2)*768 + g*4 + (k&3)] = W[g][k]
#define OFF_W0X 0
#define OFF_W0H (OFF_W0X + 8  * 768)
#define OFF_W1I (OFF_W0H + 16 * 768)
#define OFF_W1H (OFF_W1I + 16 * 768)
#define OFF_H1  (OFF_W1H + 16 * 768)              // [4 pair][2 buf][7 e][64]
#define OFF_H2  (OFF_H1 + NPAIR * 2 * EPW * Hn)
#define OFF_X   (OFF_H2 + NPAIR * 2 * EPW * Hn)   // [8 warp][7 e][32]
#define SMEM_FLOATS (OFF_X + NWARP * EPW * Dn)    // 51968 floats = 207872 B

__device__ __forceinline__ void ffma2(u64& d, u64 a, u64 b) {
    asm("fma.rn.f32x2 %0, %1, %2, %0;" : "+l"(d) : "l"(a), "l"(b));
}
__device__ __forceinline__ u64 pack2(float lo, float hi) {
    u64 r; asm("mov.b64 %0, {%1, %2};" : "=l"(r) : "f"(lo), "f"(hi)); return r;
}
__device__ __forceinline__ float hsum2(u64 v) {
    float lo, hi;
    asm("mov.b64 {%0, %1}, %2;" : "=f"(lo), "=f"(hi) : "l"(v));
    return lo + hi;
}
__device__ __forceinline__ float sigmoid_f(float x) {
    return __fdividef(1.0f, 1.0f + __expf(-x));
}
__device__ __forceinline__ float tanh_f(float x) {
    float e = __expf(-2.0f * x);
    return __fdividef(1.0f - e, 1.0f + e);
}

struct u64x2 { u64 a, b; };
__device__ __forceinline__ u64x2 lds128(const float* p) {
    u64x2 r;
    ulonglong2 v = *(const ulonglong2*)p;
    r.a = v.x; r.b = v.y;
    return r;
}

__global__ void __launch_bounds__(TPB, 1)
gru_fused_kernel(const float* __restrict__ x,
                 const float* __restrict__ W_ih0, const float* __restrict__ W_hh0,
                 const float* __restrict__ b_ih0, const float* __restrict__ b_hh0,
                 const float* __restrict__ W_ih1, const float* __restrict__ W_hh1,
                 const float* __restrict__ b_ih1, const float* __restrict__ b_hh1,
                 const float* __restrict__ fc_w, const float* __restrict__ fc_b,
                 float* __restrict__ out)
{
    extern __shared__ float sm[];
    const int tid = threadIdx.x;

    // ---- stage weights ----
    for (int idx = tid; idx < Gn * Dn; idx += TPB) {
        int g = idx / Dn, k = idx - g * Dn;
        sm[OFF_W0X + (k >> 2) * 768 + g * 4 + (k & 3)] = W_ih0[idx];
    }
    for (int idx = tid; idx < Gn * Hn; idx += TPB) {
        int g = idx / Hn, k = idx - g * Hn;
        int d = (k >> 2) * 768 + g * 4 + (k & 3);
        sm[OFF_W0H + d] = W_hh0[idx];
        sm[OFF_W1I + d] = W_ih1[idx];
        sm[OFF_W1H + d] = W_hh1[idx];
    }
    __syncthreads();

    const int warp = tid >> 5;
    const int lane = tid & 31;
    const int wg = warp >> 1;         // pair id: warps {2wg,2wg+1}
    const int hw = warp & 1;          // row half
    const int barid = 1 + wg;
    const int eb = blockIdx.x * EPB + wg * EPW;

    const int row = lane + 32 * hw;

    float* h1b = sm + OFF_H1 + wg * (2 * EPW * Hn);
    float* h2b = sm + OFF_H2 + wg * (2 * EPW * Hn);
    float* s_x = sm + OFF_X  + warp * (EPW * Dn);

#pragma unroll
    for (int e = 0; e < EPW; ++e) {
        h1b[e * Hn + row] = 0.0f;
        h2b[e * Hn + row] = 0.0f;
    }
    __syncthreads();

    // ---- PHASE STAGGER: keep pairs ~90° out of phase through the whole loop --
    {
        float dly = 1.0f;
        int iters = wg * 270;
        for (int i = 0; i < iters; ++i)
            asm volatile("fma.rn.f32 %0, %0, 0f3F800001, 0f33D6BF95;" : "+f"(dly));
    }

    // biases folded into accumulator-init constants (lo slot; hi = 0)
    const u64 BR0i  = pack2(b_ih0[row]       + b_hh0[row],       0.0f);
    const u64 BZ0i  = pack2(b_ih0[row + 64]  + b_hh0[row + 64],  0.0f);
    const u64 BXN0i = pack2(b_ih0[row + 128], 0.0f);
    const u64 BHN0i = pack2(b_hh0[row + 128], 0.0f);
    const u64 BR1i  = pack2(b_ih1[row]       + b_hh1[row],       0.0f);
    const u64 BZ1i  = pack2(b_ih1[row + 64]  + b_hh1[row + 64],  0.0f);
    const u64 BXN1i = pack2(b_ih1[row + 128], 0.0f);
    const u64 BHN1i = pack2(b_hh1[row + 128], 0.0f);

    const int oR = row * 4;
    const int oZ = (row + 64) * 4;
    const int oN = (row + 128) * 4;

    u64 ar[EPW], az[EPW], axn[EPW], ahn[EPW];

    float h1own[EPW], h2own[EPW];
#pragma unroll
    for (int e = 0; e < EPW; ++e) { h1own[e] = 0.0f; h2own[e] = 0.0f; }

    // clamped batch indices for the (early-finishing) tail block
    int be[EPW];
#pragma unroll
    for (int e = 0; e < EPW; ++e) {
        int b = eb + e;
        be[e] = (b < Bn) ? b : (Bn - 1);
    }

    // prefetch t=0 x
    float xr[EPW];
#pragma unroll
    for (int e = 0; e < EPW; ++e)
        xr[e] = x[be[e] * (Tn * Dn) + lane];

    int rd = 0;

    for (int t = 0; t < Tn; ++t) {
        const float* h1r = h1b + rd * (EPW * Hn);
        float*       h1w = h1b + (1 - rd) * (EPW * Hn);
        const float* h2r = h2b + rd * (EPW * Hn);
        float*       h2w = h2b + (1 - rd) * (EPW * Hn);

        // stage x, prefetch next t
#pragma unroll
        for (int e = 0; e < EPW; ++e)
            s_x[e * Dn + lane] = xr[e];
        __syncwarp();
        if (t + 1 < Tn) {
#pragma unroll
            for (int e = 0; e < EPW; ++e)
                xr[e] = x[(be[e] * Tn + t + 1) * Dn + lane];
        }

        // ================= layer 0 =================
#pragma unroll
        for (int e = 0; e < EPW; ++e) {
            ar[e] = BR0i; az[e] = BZ0i; axn[e] = BXN0i; ahn[e] = BHN0i;
        }

#pragma unroll 4
        for (int q = 0; q < Dn / 4; ++q) {
            const float* wq = sm + OFF_W0X + q * 768;
            u64x2 wr = lds128(wq + oR);
            u64x2 wz = lds128(wq + oZ);
            u64x2 wn = lds128(wq + oN);
            u64x2 xv[EPW];
#pragma unroll
            for (int e = 0; e < EPW; ++e)
                xv[e] = lds128(s_x + e * Dn + q * 4);
#pragma unroll
            for (int e = 0; e < EPW; ++e) {
                ffma2(ar[e],  wr.a, xv[e].a); ffma2(ar[e],  wr.b, xv[e].b);
                ffma2(az[e],  wz.a, xv[e].a); ffma2(az[e],  wz.b, xv[e].b);
                ffma2(axn[e], wn.a, xv[e].a); ffma2(axn[e], wn.b, xv[e].b);
            }
        }
#pragma unroll 4
        for (int q = 0; q < Hn / 4; ++q) {
            const float* wq = sm + OFF_W0H + q * 768;
            u64x2 wr = lds128(wq + oR);
            u64x2 wz = lds128(wq + oZ);
            u64x2 wn = lds128(wq + oN);
            u64x2 hv[EPW];
#pragma unroll
            for (int e = 0; e < EPW; ++e)
                hv[e] = lds128(h1r + e * Hn + q * 4);
#pragma unroll
            for (int e = 0; e < EPW; ++e) {
                ffma2(ar[e],  wr.a, hv[e].a); ffma2(ar[e],  wr.b, hv[e].b);
                ffma2(az[e],  wz.a, hv[e].a); ffma2(az[e],  wz.b, hv[e].b);
                ffma2(ahn[e], wn.a, hv[e].a); ffma2(ahn[e], wn.b, hv[e].b);
            }
        }

        // epilogue -> h1_new (own row)
#pragma unroll
        for (int e = 0; e < EPW; ++e) {
            float r = sigmoid_f(hsum2(ar[e]));
            float z = sigmoid_f(hsum2(az[e]));
            float n = tanh_f(fmaf(r, hsum2(ahn[e]), hsum2(axn[e])));
            float hn_ = fmaf(z, h1own[e] - n, n);
            h1own[e] = hn_;
            h1w[e * Hn + row] = hn_;
        }

        // hoist layer-1 q=0 weight loads above the barrier (static data, no race)
        u64x2 p_ir, p_iz, p_in, p_hr, p_hz, p_hn;
        {
            const float* wqi = sm + OFF_W1I;
            const float* wqh = sm + OFF_W1H;
            p_ir = lds128(wqi + oR); p_iz = lds128(wqi + oZ); p_in = lds128(wqi + oN);
            p_hr = lds128(wqh + oR); p_hz = lds128(wqh + oZ); p_hn = lds128(wqh + oN);
        }

        asm volatile("bar.sync %0, %1;" :: "r"(barid), "r"(64) : "memory");

        // ================= layer 1 =================
#pragma unroll
        for (int e = 0; e < EPW; ++e) {
            ar[e] = BR1i; az[e] = BZ1i; axn[e] = BXN1i; ahn[e] = BHN1i;
        }

        // peeled q = 0 with preloaded weights
        {
            u64x2 av[EPW], bv[EPW];
#pragma unroll
            for (int e = 0; e < EPW; ++e) {
                av[e] = lds128(h1w + e * Hn);
                bv[e] = lds128(h2r + e * Hn);
            }
#pragma unroll
            for (int e = 0; e < EPW; ++e) {
                ffma2(ar[e],  p_ir.a, av[e].a); ffma2(ar[e],  p_ir.b, av[e].b);
                ffma2(az[e],  p_iz.a, av[e].a); ffma2(az[e],  p_iz.b, av[e].b);
                ffma2(axn[e], p_in.a, av[e].a); ffma2(axn[e], p_in.b, av[e].b);
                ffma2(ar[e],  p_hr.a, bv[e].a); ffma2(ar[e],  p_hr.b, bv[e].b);
                ffma2(az[e],  p_hz.a, bv[e].a); ffma2(az[e],  p_hz.b, bv[e].b);
                ffma2(ahn[e], p_hn.a, bv[e].a); ffma2(ahn[e], p_hn.b, bv[e].b);
            }
        }

#pragma unroll 3
        for (int q = 1; q < Hn / 4; ++q) {
            const float* wqi = sm + OFF_W1I + q * 768;
            const float* wqh = sm + OFF_W1H + q * 768;
            u64x2 ir = lds128(wqi + oR);
            u64x2 iz = lds128(wqi + oZ);
            u64x2 in = lds128(wqi + oN);
            u64x2 hr = lds128(wqh + oR);
            u64x2 hz = lds128(wqh + oZ);
            u64x2 hn = lds128(wqh + oN);
            u64x2 av[EPW], bv[EPW];
#pragma unroll
            for (int e = 0; e < EPW; ++e) {
                av[e] = lds128(h1w + e * Hn + q * 4);
                bv[e] = lds128(h2r + e * Hn + q * 4);
            }
#pragma unroll
            for (int e = 0; e < EPW; ++e) {
                ffma2(ar[e],  ir.a, av[e].a); ffma2(ar[e],  ir.b, av[e].b);
                ffma2(az[e],  iz.a, av[e].a); ffma2(az[e],  iz.b, av[e].b);
                ffma2(axn[e], in.a, av[e].a); ffma2(axn[e], in.b, av[e].b);
                ffma2(ar[e],  hr.a, bv[e].a); ffma2(ar[e],  hr.b, bv[e].b);
                ffma2(az[e],  hz.a, bv[e].a); ffma2(az[e],  hz.b, bv[e].b);
                ffma2(ahn[e], hn.a, bv[e].a); ffma2(ahn[e], hn.b, bv[e].b);
            }
        }

#pragma unroll
        for (int e = 0; e < EPW; ++e) {
            float r = sigmoid_f(hsum2(ar[e]));
            float z = sigmoid_f(hsum2(az[e]));
            float n = tanh_f(fmaf(r, hsum2(ahn[e]), hsum2(axn[e])));
            float hn_ = fmaf(z, h2own[e] - n, n);
            h2own[e] = hn_;
            h2w[e * Hn + row] = hn_;
        }

        rd ^= 1;
    }

    asm volatile("bar.sync %0, %1;" :: "r"(barid), "r"(64) : "memory");

    // ---- FC head ----
    if (hw == 0) {
        const float* h2f = h2b + rd * (EPW * Hn);
        const float fw0 = fc_w[lane];
        const float fw1 = fc_w[lane + 32];
        const float fb  = fc_b[0];
#pragma unroll
        for (int e = 0; e < EPW; ++e) {
            float v = fw0 * h2own[e] + fw1 * h2f[e * Hn + lane + 32];
#pragma unroll
            for (int off = 16; off > 0; off >>= 1)
                v += __shfl_xor_sync(0xffffffffu, v, off);
            if (lane == 0 && eb + e < Bn) out[eb + e] = v + fb;
        }
    }
}

extern "C" void kernel_launch(void* const* d_in, const int* in_sizes, int n_in,
                              void* d_out, int out_size)
{
    const float* x     = (const float*)d_in[0];
    const float* W_ih0 = (const float*)d_in[1];
    const float* W_hh0 = (const float*)d_in[2];
    const float* b_ih0 = (const float*)d_in[3];
    const float* b_hh0 = (const float*)d_in[4];
    const float* W_ih1 = (const float*)d_in[5];
    const float* W_hh1 = (const float*)d_in[6];
    const float* b_ih1 = (const float*)d_in[7];
    const float* b_hh1 = (const float*)d_in[8];
    const float* fc_w  = (const float*)d_in[9];
    const float* fc_b  = (const float*)d_in[10];
    float* out = (float*)d_out;

    int batch = in_sizes[0] / (Tn * Dn);          // 4096
    int grid = (batch + EPB - 1) / EPB;           // 147 blocks (~full wave)

    size_t smem = (size_t)SMEM_FLOATS * sizeof(float);  // 207872 B
    cudaFuncSetAttribute(gru_fused_kernel,
                         cudaFuncAttributeMaxDynamicSharedMemorySize, (int)smem);

    gru_fused_kernel<<<grid, TPB, smem>>>(x, W_ih0, W_hh0, b_ih0, b_hh0,
                                          W_ih1, W_hh1, b_ih1, b_hh1,
                                          fc_w, fc_b, out);
}

// round 16
// speedup vs baseline: 1.2338x; 1.0337x over previous
#include <cuda_runtime.h>

typedef unsigned long long u64;

#define Bn 4096
#define Tn 128
#define Dn 32
#define Hn 64
#define Gn 192   // 3*H

#define NWARP 8
#define TPB (NWARP * 32)  // 256 threads
#define NPAIR 4           // warp pairs per block
#define EPW 7             // batch elements per warp PAIR
#define EPB (NPAIR * EPW) // 28 elements per block -> grid 147 (~full 148-SM wave)

// Weight layout: s[(k>>2)*768 + g*4 + (k&3)] = W[g][k]
#define OFF_W0X 0
#define OFF_W0H (OFF_W0X + 8  * 768)
#define OFF_W1I (OFF_W0H + 16 * 768)
#define OFF_W1H (OFF_W1I + 16 * 768)
#define OFF_H1  (OFF_W1H + 16 * 768)              // [4 pair][2 buf][7 e][64]
#define OFF_H2  (OFF_H1 + NPAIR * 2 * EPW * Hn)
#define OFF_X   (OFF_H2 + NPAIR * 2 * EPW * Hn)   // [8 warp][7 e][32]
#define SMEM_FLOATS (OFF_X + NWARP * EPW * Dn)    // 51968 floats = 207872 B

__device__ __forceinline__ void ffma2(u64& d, u64 a, u64 b) {
    asm("fma.rn.f32x2 %0, %1, %2, %0;" : "+l"(d) : "l"(a), "l"(b));
}
__device__ __forceinline__ u64 pack2(float lo, float hi) {
    u64 r; asm("mov.b64 %0, {%1, %2};" : "=l"(r) : "f"(lo), "f"(hi)); return r;
}
__device__ __forceinline__ float hsum2(u64 v) {
    float lo, hi;
    asm("mov.b64 {%0, %1}, %2;" : "=f"(lo), "=f"(hi) : "l"(v));
    return lo + hi;
}

// HW tanh (MUFU.TANH, single op, sm_75+; max err ~2^-11)
__device__ __forceinline__ float tanh_hw(float x) {
    float y; asm("tanh.approx.f32 %0, %1;" : "=f"(y) : "f"(x)); return y;
}
// sigmoid(x) = 0.5 * tanh(0.5 x) + 0.5  (one MUFU + FMUL + FFMA)
__device__ __forceinline__ float sigmoid_f(float x) {
    return fmaf(0.5f, tanh_hw(0.5f * x), 0.5f);
}
__device__ __forceinline__ float tanh_f(float x) {
    return tanh_hw(x);
}

struct u64x2 { u64 a, b; };
__device__ __forceinline__ u64x2 lds128(const float* p) {
    u64x2 r;
    ulonglong2 v = *(const ulonglong2*)p;
    r.a = v.x; r.b = v.y;
    return r;
}

__global__ void __launch_bounds__(TPB, 1)
gru_fused_kernel(const float* __restrict__ x,
                 const float* __restrict__ W_ih0, const float* __restrict__ W_hh0,
                 const float* __restrict__ b_ih0, const float* __restrict__ b_hh0,
                 const float* __restrict__ W_ih1, const float* __restrict__ W_hh1,
                 const float* __restrict__ b_ih1, const float* __restrict__ b_hh1,
                 const float* __restrict__ fc_w, const float* __restrict__ fc_b,
                 float* __restrict__ out)
{
    extern __shared__ float sm[];
    const int tid = threadIdx.x;

    // ---- stage weights ----
    for (int idx = tid; idx < Gn * Dn; idx += TPB) {
        int g = idx / Dn, k = idx - g * Dn;
        sm[OFF_W0X + (k >> 2) * 768 + g * 4 + (k & 3)] = W_ih0[idx];
    }
    for (int idx = tid; idx < Gn * Hn; idx += TPB) {
        int g = idx / Hn, k = idx - g * Hn;
        int d = (k >> 2) * 768 + g * 4 + (k & 3);
        sm[OFF_W0H + d] = W_hh0[idx];
        sm[OFF_W1I + d] = W_ih1[idx];
        sm[OFF_W1H + d] = W_hh1[idx];
    }
    __syncthreads();

    const int warp = tid >> 5;
    const int lane = tid & 31;
    const int wg = warp >> 1;         // pair id: warps {2wg,2wg+1}
    const int hw = warp & 1;          // row half
    const int barid = 1 + wg;
    const int eb = blockIdx.x * EPB + wg * EPW;

    const int row = lane + 32 * hw;

    float* h1b = sm + OFF_H1 + wg * (2 * EPW * Hn);
    float* h2b = sm + OFF_H2 + wg * (2 * EPW * Hn);
    float* s_x = sm + OFF_X  + warp * (EPW * Dn);

#pragma unroll
    for (int e = 0; e < EPW; ++e) {
        h1b[e * Hn + row] = 0.0f;
        h2b[e * Hn + row] = 0.0f;
    }
    __syncthreads();

    // ---- PHASE STAGGER: keep pairs ~90° out of phase through the whole loop --
    {
        float dly = 1.0f;
        int iters = wg * 270;
        for (int i = 0; i < iters; ++i)
            asm volatile("fma.rn.f32 %0, %0, 0f3F800001, 0f33D6BF95;" : "+f"(dly));
    }

    // biases folded into accumulator-init constants (lo slot; hi = 0)
    const u64 BR0i  = pack2(b_ih0[row]       + b_hh0[row],       0.0f);
    const u64 BZ0i  = pack2(b_ih0[row + 64]  + b_hh0[row + 64],  0.0f);
    const u64 BXN0i = pack2(b_ih0[row + 128], 0.0f);
    const u64 BHN0i = pack2(b_hh0[row + 128], 0.0f);
    const u64 BR1i  = pack2(b_ih1[row]       + b_hh1[row],       0.0f);
    const u64 BZ1i  = pack2(b_ih1[row + 64]  + b_hh1[row + 64],  0.0f);
    const u64 BXN1i = pack2(b_ih1[row + 128], 0.0f);
    const u64 BHN1i = pack2(b_hh1[row + 128], 0.0f);

    const int oR = row * 4;
    const int oZ = (row + 64) * 4;
    const int oN = (row + 128) * 4;

    u64 ar[EPW], az[EPW], axn[EPW], ahn[EPW];

    float h1own[EPW], h2own[EPW];
#pragma unroll
    for (int e = 0; e < EPW; ++e) { h1own[e] = 0.0f; h2own[e] = 0.0f; }

    // clamped batch indices for the (early-finishing) tail block
    int be[EPW];
#pragma unroll
    for (int e = 0; e < EPW; ++e) {
        int b = eb + e;
        be[e] = (b < Bn) ? b : (Bn - 1);
    }

    // prefetch t=0 x
    float xr[EPW];
#pragma unroll
    for (int e = 0; e < EPW; ++e)
        xr[e] = x[be[e] * (Tn * Dn) + lane];

    int rd = 0;

    for (int t = 0; t < Tn; ++t) {
        const float* h1r = h1b + rd * (EPW * Hn);
        float*       h1w = h1b + (1 - rd) * (EPW * Hn);
        const float* h2r = h2b + rd * (EPW * Hn);
        float*       h2w = h2b + (1 - rd) * (EPW * Hn);

        // stage x, prefetch next t
#pragma unroll
        for (int e = 0; e < EPW; ++e)
            s_x[e * Dn + lane] = xr[e];
        __syncwarp();
        if (t + 1 < Tn) {
#pragma unroll
            for (int e = 0; e < EPW; ++e)
                xr[e] = x[(be[e] * Tn + t + 1) * Dn + lane];
        }

        // ================= layer 0 =================
#pragma unroll
        for (int e = 0; e < EPW; ++e) {
            ar[e] = BR0i; az[e] = BZ0i; axn[e] = BXN0i; ahn[e] = BHN0i;
        }

#pragma unroll 4
        for (int q = 0; q < Dn / 4; ++q) {
            const float* wq = sm + OFF_W0X + q * 768;
            u64x2 wr = lds128(wq + oR);
            u64x2 wz = lds128(wq + oZ);
            u64x2 wn = lds128(wq + oN);
            u64x2 xv[EPW];
#pragma unroll
            for (int e = 0; e < EPW; ++e)
                xv[e] = lds128(s_x + e * Dn + q * 4);
#pragma unroll
            for (int e = 0; e < EPW; ++e) {
                ffma2(ar[e],  wr.a, xv[e].a); ffma2(ar[e],  wr.b, xv[e].b);
                ffma2(az[e],  wz.a, xv[e].a); ffma2(az[e],  wz.b, xv[e].b);
                ffma2(axn[e], wn.a, xv[e].a); ffma2(axn[e], wn.b, xv[e].b);
            }
        }
#pragma unroll 4
        for (int q = 0; q < Hn / 4; ++q) {
            const float* wq = sm + OFF_W0H + q * 768;
            u64x2 wr = lds128(wq + oR);
            u64x2 wz = lds128(wq + oZ);
            u64x2 wn = lds128(wq + oN);
            u64x2 hv[EPW];
#pragma unroll
            for (int e = 0; e < EPW; ++e)
                hv[e] = lds128(h1r + e * Hn + q * 4);
#pragma unroll
            for (int e = 0; e < EPW; ++e) {
                ffma2(ar[e],  wr.a, hv[e].a); ffma2(ar[e],  wr.b, hv[e].b);
                ffma2(az[e],  wz.a, hv[e].a); ffma2(az[e],  wz.b, hv[e].b);
                ffma2(ahn[e], wn.a, hv[e].a); ffma2(ahn[e], wn.b, hv[e].b);
            }
        }

        // epilogue -> h1_new (own row)
#pragma unroll
        for (int e = 0; e < EPW; ++e) {
            float r = sigmoid_f(hsum2(ar[e]));
            float z = sigmoid_f(hsum2(az[e]));
            float n = tanh_f(fmaf(r, hsum2(ahn[e]), hsum2(axn[e])));
            float hn_ = fmaf(z, h1own[e] - n, n);
            h1own[e] = hn_;
            h1w[e * Hn + row] = hn_;
        }

        // hoist layer-1 q=0 weight loads above the barrier (static data, no race)
        u64x2 p_ir, p_iz, p_in, p_hr, p_hz, p_hn;
        {
            const float* wqi = sm + OFF_W1I;
            const float* wqh = sm + OFF_W1H;
            p_ir = lds128(wqi + oR); p_iz = lds128(wqi + oZ); p_in = lds128(wqi + oN);
            p_hr = lds128(wqh + oR); p_hz = lds128(wqh + oZ); p_hn = lds128(wqh + oN);
        }

        asm volatile("bar.sync %0, %1;" :: "r"(barid), "r"(64) : "memory");

        // ================= layer 1 =================
#pragma unroll
        for (int e = 0; e < EPW; ++e) {
            ar[e] = BR1i; az[e] = BZ1i; axn[e] = BXN1i; ahn[e] = BHN1i;
        }

        // peeled q = 0 with preloaded weights
        {
            u64x2 av[EPW], bv[EPW];
#pragma unroll
            for (int e = 0; e < EPW; ++e) {
                av[e] = lds128(h1w + e * Hn);
                bv[e] = lds128(h2r + e * Hn);
            }
#pragma unroll
            for (int e = 0; e < EPW; ++e) {
                ffma2(ar[e],  p_ir.a, av[e].a); ffma2(ar[e],  p_ir.b, av[e].b);
                ffma2(az[e],  p_iz.a, av[e].a); ffma2(az[e],  p_iz.b, av[e].b);
                ffma2(axn[e], p_in.a, av[e].a); ffma2(axn[e], p_in.b, av[e].b);
                ffma2(ar[e],  p_hr.a, bv[e].a); ffma2(ar[e],  p_hr.b, bv[e].b);
                ffma2(az[e],  p_hz.a, bv[e].a); ffma2(az[e],  p_hz.b, bv[e].b);
                ffma2(ahn[e], p_hn.a, bv[e].a); ffma2(ahn[e], p_hn.b, bv[e].b);
            }
        }

#pragma unroll 3
        for (int q = 1; q < Hn / 4; ++q) {
            const float* wqi = sm + OFF_W1I + q * 768;
            const float* wqh = sm + OFF_W1H + q * 768;
            u64x2 ir = lds128(wqi + oR);
            u64x2 iz = lds128(wqi + oZ);
            u64x2 in = lds128(wqi + oN);
            u64x2 hr = lds128(wqh + oR);
            u64x2 hz = lds128(wqh + oZ);
            u64x2 hn = lds128(wqh + oN);
            u64x2 av[EPW], bv[EPW];
#pragma unroll
            for (int e = 0; e < EPW; ++e) {
                av[e] = lds128(h1w + e * Hn + q * 4);
                bv[e] = lds128(h2r + e * Hn + q * 4);
            }
#pragma unroll
            for (int e = 0; e < EPW; ++e) {
                ffma2(ar[e],  ir.a, av[e].a); ffma2(ar[e],  ir.b, av[e].b);
                ffma2(az[e],  iz.a, av[e].a); ffma2(az[e],  iz.b, av[e].b);
                ffma2(axn[e], in.a, av[e].a); ffma2(axn[e], in.b, av[e].b);
                ffma2(ar[e],  hr.a, bv[e].a); ffma2(ar[e],  hr.b, bv[e].b);
                ffma2(az[e],  hz.a, bv[e].a); ffma2(az[e],  hz.b, bv[e].b);
                ffma2(ahn[e], hn.a, bv[e].a); ffma2(ahn[e], hn.b, bv[e].b);
            }
        }

#pragma unroll
        for (int e = 0; e < EPW; ++e) {
            float r = sigmoid_f(hsum2(ar[e]));
            float z = sigmoid_f(hsum2(az[e]));
            float n = tanh_f(fmaf(r, hsum2(ahn[e]), hsum2(axn[e])));
            float hn_ = fmaf(z, h2own[e] - n, n);
            h2own[e] = hn_;
            h2w[e * Hn + row] = hn_;
        }

        rd ^= 1;
    }

    asm volatile("bar.sync %0, %1;" :: "r"(barid), "r"(64) : "memory");

    // ---- FC head ----
    if (hw == 0) {
        const float* h2f = h2b + rd * (EPW * Hn);
        const float fw0 = fc_w[lane];
        const float fw1 = fc_w[lane + 32];
        const float fb  = fc_b[0];
#pragma unroll
        for (int e = 0; e < EPW; ++e) {
            float v = fw0 * h2own[e] + fw1 * h2f[e * Hn + lane + 32];
#pragma unroll
            for (int off = 16; off > 0; off >>= 1)
                v += __shfl_xor_sync(0xffffffffu, v, off);
            if (lane == 0 && eb + e < Bn) out[eb + e] = v + fb;
        }
    }
}

extern "C" void kernel_launch(void* const* d_in, const int* in_sizes, int n_in,
                              void* d_out, int out_size)
{
    const float* x     = (const float*)d_in[0];
    const float* W_ih0 = (const float*)d_in[1];
    const float* W_hh0 = (const float*)d_in[2];
    const float* b_ih0 = (const float*)d_in[3];
    const float* b_hh0 = (const float*)d_in[4];
    const float* W_ih1 = (const float*)d_in[5];
    const float* W_hh1 = (const float*)d_in[6];
    const float* b_ih1 = (const float*)d_in[7];
    const float* b_hh1 = (const float*)d_in[8];
    const float* fc_w  = (const float*)d_in[9];
    const float* fc_b  = (const float*)d_in[10];
    float* out = (float*)d_out;

    int batch = in_sizes[0] / (Tn * Dn);          // 4096
    int grid = (batch + EPB - 1) / EPB;           // 147 blocks (~full wave)

    size_t smem = (size_t)SMEM_FLOATS * sizeof(float);  // 207872 B
    cudaFuncSetAttribute(gru_fused_kernel,
                         cudaFuncAttributeMaxDynamicSharedMemorySize, (int)smem);

    gru_fused_kernel<<<grid, TPB, smem>>>(x, W_ih0, W_hh0, b_ih0, b_hh0,
                                          W_ih1, W_hh1, b_ih1, b_hh1,
                                          fc_w, fc_b, out);
}